// round 12
// baseline (speedup 1.0000x reference)
#include <cuda_runtime.h>
#include <cuda_fp16.h>
#include <mma.h>

using namespace nvcuda;

#define NMAX 100000
#define EMAX 1600000
#define HD 64

// Scratch (device globals — allocation-free per harness rules)
__device__ float  g_deg[NMAX];            // degree, then dinv (in place)
__device__ __half g_hwh [NMAX * HD];      // layer-1 h @ W1 (fp16)
__device__ __half g_hwh2[NMAX * HD];      // layer-2 h1 @ W2 (fp16)
__device__ float  g_pool[HD];             // feature sums for mean pool
// CSR build
__device__ int    g_cnt [NMAX];           // per-row edge count
__device__ int    g_cur [NMAX];           // fill cursor
__device__ int    g_start[NMAX + 1];      // row offsets (pre-boff, per-1024-chunk local)
__device__ int    g_bsum[128];            // scan partials
__device__ int    g_boff[128];            // scan partial offsets
__device__ int    g_done;                 // scan last-block detector
__device__ int2   g_edat[EMAX];           // (col, norm-bits) in row-grouped order

// ---------------------------------------------------------------------------
__global__ void k_prep(int n) {
    int i = blockIdx.x * blockDim.x + threadIdx.x;
    int stride = gridDim.x * blockDim.x;
    for (int j = i; j < n; j += stride) { g_cnt[j] = 0; g_cur[j] = 0; g_deg[j] = 1.0f; }
    if (i < HD) g_pool[i] = 0.f;
    if (i == 0) g_done = 0;
}

// deg[row] += attr ; cnt[row]++
__global__ void k_deg_hist(const int* __restrict__ rowp, const float* __restrict__ attr, int e) {
    int i = blockIdx.x * blockDim.x + threadIdx.x;
    if (i < e) {
        int r = rowp[i];
        atomicAdd(&g_deg[r], attr[i]);
        atomicAdd(&g_cnt[r], 1);
    }
}

// ---------------------------------------------------------------------------
// Single-kernel scan: per-1024-chunk exclusive scan of g_cnt into g_start,
// fused dinv, and the LAST finishing block scans the <=128 chunk totals into
// g_boff (decoupled final step; consumers add g_boff[idx>>10] on the fly).
__global__ void k_scan1(int n) {
    __shared__ int ts[256];
    __shared__ int s_isLast;
    int tid = threadIdx.x;
    int base = blockIdx.x * 1024 + tid * 4;
    int v[4]; int s = 0;
#pragma unroll
    for (int i = 0; i < 4; i++) {
        int idx = base + i;
        v[i] = (idx < n) ? g_cnt[idx] : 0;
        s += v[i];
        if (idx < n) g_deg[idx] = rsqrtf(g_deg[idx]);   // fused dinv
    }
    ts[tid] = s;
    __syncthreads();
    for (int off = 1; off < 256; off <<= 1) {
        int y = (tid >= off) ? ts[tid - off] : 0;
        __syncthreads();
        ts[tid] += y;
        __syncthreads();
    }
    int run = ts[tid] - s;   // exclusive within chunk
#pragma unroll
    for (int i = 0; i < 4; i++) {
        int idx = base + i;
        if (idx < n) g_start[idx] = run;
        run += v[i];
    }
    if (tid == 255) g_bsum[blockIdx.x] = ts[255];
    __syncthreads();
    if (tid == 0) {
        __threadfence();
        s_isLast = (atomicAdd(&g_done, 1) == (int)gridDim.x - 1);
    }
    __syncthreads();
    if (s_isLast && tid < 32) {
        int nb = gridDim.x;
        volatile const int* bs = g_bsum;
        int w[4]; int sum = 0;
#pragma unroll
        for (int i = 0; i < 4; i++) {
            int idx = tid * 4 + i;
            w[i] = (idx < nb) ? bs[idx] : 0;
            sum += w[i];
        }
        int inc = sum;
#pragma unroll
        for (int off = 1; off < 32; off <<= 1) {
            int y = __shfl_up_sync(0xFFFFFFFFu, inc, off);
            if (tid >= off) inc += y;
        }
        int r2 = inc - sum;
#pragma unroll
        for (int i = 0; i < 4; i++) {
            int idx = tid * 4 + i;
            if (idx < nb) g_boff[idx] = r2;
            r2 += w[i];
        }
    }
}

// fill CSR: (col, norm) per edge, grouped by row; boff applied on the fly
__global__ void k_fill(const int* __restrict__ rowp, const int* __restrict__ colp,
                       const float* __restrict__ attr, int e) {
    int i = blockIdx.x * blockDim.x + threadIdx.x;
    if (i < e) {
        int r = rowp[i], c = colp[i];
        int pos = g_start[r] + g_boff[r >> 10] + atomicAdd(&g_cur[r], 1);
        float nrm = g_deg[r] * attr[i] * g_deg[c];
        g_edat[pos] = make_int2(c, __float_as_int(nrm));
    }
}

// ---------------------------------------------------------------------------
// row range helper (boff applied on the fly; idx==n uses e directly)
__device__ __forceinline__ int row_start(int node) {
    return g_start[node] + g_boff[node >> 10];
}

// ---------------------------------------------------------------------------
// GEMM (tensor core): g_hwh = x @ W1 (fp32 in converted to fp16, fp32 acc).
// 256 threads = 8 warps; 128 rows/block; warp = 16 rows x 64 cols.
// XLD = 80 halves (160 B): every wmma fragment pointer is 32-byte aligned.
#define XLD 80
__global__ void __launch_bounds__(256) k_gemm(const float* __restrict__ inp,
                                              const float* __restrict__ W, int n) {
    __shared__ __align__(32) __half sW[64 * XLD];
    __shared__ __align__(32) __half sX[128 * XLD];
    __shared__ __align__(16) float  sOut[8][16 * 16];
    int tid = threadIdx.x;
    int wid = tid >> 5, lane = tid & 31;

    for (int j = tid; j < 1024; j += 256) {
        int r = j >> 4, c4 = (j & 15) * 4;
        float4 v = *(const float4*)(W + r * 64 + c4);
        __half2* d = (__half2*)&sW[r * XLD + c4];
        d[0] = __floats2half2_rn(v.x, v.y);
        d[1] = __floats2half2_rn(v.z, v.w);
    }
    int rowBase = blockIdx.x * 128;
    for (int j = tid; j < 2048; j += 256) {
        int r = j >> 4, c4 = (j & 15) * 4;
        int gr = rowBase + r;
        float4 v = (gr < n) ? *(const float4*)(inp + (size_t)gr * 64 + c4)
                            : make_float4(0.f, 0.f, 0.f, 0.f);
        __half2* d = (__half2*)&sX[r * XLD + c4];
        d[0] = __floats2half2_rn(v.x, v.y);
        d[1] = __floats2half2_rn(v.z, v.w);
    }
    __syncthreads();

    wmma::fragment<wmma::accumulator, 16, 16, 16, float> acc[4];
#pragma unroll
    for (int t = 0; t < 4; t++) wmma::fill_fragment(acc[t], 0.f);
#pragma unroll
    for (int kk = 0; kk < 4; kk++) {
        wmma::fragment<wmma::matrix_a, 16, 16, 16, __half, wmma::row_major> a;
        wmma::load_matrix_sync(a, &sX[(wid * 16) * XLD + kk * 16], XLD);
#pragma unroll
        for (int t = 0; t < 4; t++) {
            wmma::fragment<wmma::matrix_b, 16, 16, 16, __half, wmma::row_major> b;
            wmma::load_matrix_sync(b, &sW[(kk * 16) * XLD + t * 16], XLD);
            wmma::mma_sync(acc[t], a, b, acc[t]);
        }
    }

    int r0 = rowBase + wid * 16;
    int rr = lane >> 1, cc = (lane & 1) * 8;
#pragma unroll
    for (int t = 0; t < 4; t++) {
        wmma::store_matrix_sync(sOut[wid], acc[t], 16, wmma::mem_row_major);
        __syncwarp();
        if (r0 + rr < n) {
            const float* src = &sOut[wid][rr * 16 + cc];
            __half2 h0 = __floats2half2_rn(src[0], src[1]);
            __half2 h1 = __floats2half2_rn(src[2], src[3]);
            __half2 h2 = __floats2half2_rn(src[4], src[5]);
            __half2 h3 = __floats2half2_rn(src[6], src[7]);
            uint4 u;
            u.x = *(unsigned int*)&h0; u.y = *(unsigned int*)&h1;
            u.z = *(unsigned int*)&h2; u.w = *(unsigned int*)&h3;
            *(uint4*)&g_hwh[(size_t)(r0 + rr) * 64 + t * 16 + cc] = u;
        }
        __syncwarp();
    }
}

// ---------------------------------------------------------------------------
// FUSED layer-1 aggregation + layer-2 GEMM.
// Phase 1: 8 warps x 16 nodes each; warp-per-node gather from g_hwh (layer-1),
//          self-loop + b1 + relu, fp16 result straight into the smem X tile.
// Phase 2: wmma X @ W2 -> g_hwh2 (separate buffer: no race with other blocks
//          still gathering layer-1 g_hwh).
__global__ void __launch_bounds__(256) k_agg_gemm(const float* __restrict__ bias,
                                                  const float* __restrict__ W,
                                                  int n, int e) {
    __shared__ __align__(32) __half sW[64 * XLD];
    __shared__ __align__(32) __half sX[128 * XLD];
    __shared__ __align__(16) float  sOut[8][16 * 16];
    int tid = threadIdx.x;
    int wid = tid >> 5, lane = tid & 31;

    for (int j = tid; j < 1024; j += 256) {
        int r = j >> 4, c4 = (j & 15) * 4;
        float4 v = *(const float4*)(W + r * 64 + c4);
        __half2* d = (__half2*)&sW[r * XLD + c4];
        d[0] = __floats2half2_rn(v.x, v.y);
        d[1] = __floats2half2_rn(v.z, v.w);
    }

    int rowBase = blockIdx.x * 128;
    const __half2* hwh2 = (const __half2*)g_hwh;
    float2 b = *(const float2*)&bias[lane * 2];

    for (int i = 0; i < 16; i++) {
        int local_r = wid * 16 + i;
        int node = rowBase + local_r;
        float2 acc = make_float2(0.f, 0.f);
        if (node < n) {
            int s   = row_start(node);
            int end = (node == n - 1) ? e : row_start(node + 1);
            int j = s;
            for (; j + 4 <= end; j += 4) {
                int2 e0 = g_edat[j],     e1 = g_edat[j + 1];
                int2 e2 = g_edat[j + 2], e3 = g_edat[j + 3];
                float2 f0 = __half22float2(hwh2[(size_t)e0.x * 32 + lane]);
                float2 f1 = __half22float2(hwh2[(size_t)e1.x * 32 + lane]);
                float2 f2 = __half22float2(hwh2[(size_t)e2.x * 32 + lane]);
                float2 f3 = __half22float2(hwh2[(size_t)e3.x * 32 + lane]);
                float n0 = __int_as_float(e0.y), n1 = __int_as_float(e1.y);
                float n2 = __int_as_float(e2.y), n3 = __int_as_float(e3.y);
                acc.x += n0 * f0.x + n1 * f1.x + n2 * f2.x + n3 * f3.x;
                acc.y += n0 * f0.y + n1 * f1.y + n2 * f2.y + n3 * f3.y;
            }
            for (; j < end; j++) {
                int2 ed = g_edat[j];
                float2 f = __half22float2(hwh2[(size_t)ed.x * 32 + lane]);
                float nm = __int_as_float(ed.y);
                acc.x += nm * f.x;
                acc.y += nm * f.y;
            }
            float d  = g_deg[node];
            float sl = d * d;
            float2 hw = __half22float2(hwh2[(size_t)node * 32 + lane]);
            acc.x = fmaxf(acc.x + sl * hw.x + b.x, 0.f);
            acc.y = fmaxf(acc.y + sl * hw.y + b.y, 0.f);
        }
        *(__half2*)&sX[local_r * XLD + lane * 2] = __floats2half2_rn(acc.x, acc.y);
    }
    __syncthreads();

    wmma::fragment<wmma::accumulator, 16, 16, 16, float> acc[4];
#pragma unroll
    for (int t = 0; t < 4; t++) wmma::fill_fragment(acc[t], 0.f);
#pragma unroll
    for (int kk = 0; kk < 4; kk++) {
        wmma::fragment<wmma::matrix_a, 16, 16, 16, __half, wmma::row_major> a;
        wmma::load_matrix_sync(a, &sX[(wid * 16) * XLD + kk * 16], XLD);
#pragma unroll
        for (int t = 0; t < 4; t++) {
            wmma::fragment<wmma::matrix_b, 16, 16, 16, __half, wmma::row_major> bb;
            wmma::load_matrix_sync(bb, &sW[(kk * 16) * XLD + t * 16], XLD);
            wmma::mma_sync(acc[t], a, bb, acc[t]);
        }
    }

    int r0 = rowBase + wid * 16;
    int rr = lane >> 1, cc = (lane & 1) * 8;
#pragma unroll
    for (int t = 0; t < 4; t++) {
        wmma::store_matrix_sync(sOut[wid], acc[t], 16, wmma::mem_row_major);
        __syncwarp();
        if (r0 + rr < n) {
            const float* src = &sOut[wid][rr * 16 + cc];
            __half2 h0 = __floats2half2_rn(src[0], src[1]);
            __half2 h1 = __floats2half2_rn(src[2], src[3]);
            __half2 h2 = __floats2half2_rn(src[4], src[5]);
            __half2 h3 = __floats2half2_rn(src[6], src[7]);
            uint4 u;
            u.x = *(unsigned int*)&h0; u.y = *(unsigned int*)&h1;
            u.z = *(unsigned int*)&h2; u.w = *(unsigned int*)&h3;
            *(uint4*)&g_hwh2[(size_t)(r0 + rr) * 64 + t * 16 + cc] = u;
        }
        __syncwarp();
    }
}

// ---------------------------------------------------------------------------
// Layer-2 aggregation + mean-pool accumulation (reads g_hwh2).
__global__ void __launch_bounds__(256) k_agg_pool(const float* __restrict__ bias,
                                                  int n, int e) {
    int lane = threadIdx.x & 31;
    int wid  = threadIdx.x >> 5;
    int node = blockIdx.x * 8 + wid;
    const __half2* hwh2 = (const __half2*)g_hwh2;

    float2 acc = make_float2(0.f, 0.f);
    if (node < n) {
        int s   = row_start(node);
        int end = (node == n - 1) ? e : row_start(node + 1);
        int j = s;
        for (; j + 4 <= end; j += 4) {
            int2 e0 = g_edat[j],     e1 = g_edat[j + 1];
            int2 e2 = g_edat[j + 2], e3 = g_edat[j + 3];
            float2 f0 = __half22float2(hwh2[(size_t)e0.x * 32 + lane]);
            float2 f1 = __half22float2(hwh2[(size_t)e1.x * 32 + lane]);
            float2 f2 = __half22float2(hwh2[(size_t)e2.x * 32 + lane]);
            float2 f3 = __half22float2(hwh2[(size_t)e3.x * 32 + lane]);
            float n0 = __int_as_float(e0.y), n1 = __int_as_float(e1.y);
            float n2 = __int_as_float(e2.y), n3 = __int_as_float(e3.y);
            acc.x += n0 * f0.x + n1 * f1.x + n2 * f2.x + n3 * f3.x;
            acc.y += n0 * f0.y + n1 * f1.y + n2 * f2.y + n3 * f3.y;
        }
        for (; j < end; j++) {
            int2 ed = g_edat[j];
            float2 f = __half22float2(hwh2[(size_t)ed.x * 32 + lane]);
            float nm = __int_as_float(ed.y);
            acc.x += nm * f.x;
            acc.y += nm * f.y;
        }
        float d  = g_deg[node];
        float sl = d * d;
        float2 hw = __half22float2(hwh2[(size_t)node * 32 + lane]);
        float2 b  = *(const float2*)&bias[lane * 2];
        acc.x = fmaxf(acc.x + sl * hw.x + b.x, 0.f);
        acc.y = fmaxf(acc.y + sl * hw.y + b.y, 0.f);
    }

    __shared__ float2 sred[256];
    sred[threadIdx.x] = acc;
    __syncthreads();
    if (wid == 0) {
        float2 t = sred[lane];
#pragma unroll
        for (int w = 1; w < 8; w++) {
            float2 v = sred[w * 32 + lane];
            t.x += v.x; t.y += v.y;
        }
        float* dst = &g_pool[lane * 2];
        asm volatile("red.global.add.v2.f32 [%0], {%1,%2};"
                     :: "l"(dst), "f"(t.x), "f"(t.y) : "memory");
    }
}

// ---------------------------------------------------------------------------
// head: z = [pool/n, h_other];  out = relu(z@Wc1+bc1) @ Wc2 + bc2
__global__ void k_head(const float* __restrict__ Wc1, const float* __restrict__ bc1,
                       const float* __restrict__ Wc2, const float* __restrict__ bc2,
                       const float* __restrict__ h_other, float* __restrict__ out, int n) {
    __shared__ float z[128];
    __shared__ float hid[64];
    int t = threadIdx.x;
    if (t < 64) {
        z[t]      = g_pool[t] / (float)n;
        z[64 + t] = h_other[t];
    }
    __syncthreads();
    if (t < 64) {
        float s = bc1[t];
#pragma unroll 8
        for (int i = 0; i < 128; i++) s += z[i] * Wc1[i * 64 + t];
        hid[t] = fmaxf(s, 0.f);
    }
    __syncthreads();
    if (t < 3) {
        float s = bc2[t];
#pragma unroll
        for (int j = 0; j < 64; j++) s += hid[j] * Wc2[j * 3 + t];
        out[t] = s;
    }
}

// ---------------------------------------------------------------------------
extern "C" void kernel_launch(void* const* d_in, const int* in_sizes, int n_in,
                              void* d_out, int out_size) {
    const float* x        = (const float*)d_in[0];
    const int*   eidx     = (const int*)  d_in[1];
    const float* eattr    = (const float*)d_in[2];
    // d_in[3] = batch (unused; single graph)
    const float* W1       = (const float*)d_in[4];
    const float* b1       = (const float*)d_in[5];
    const float* W2       = (const float*)d_in[6];
    const float* b2       = (const float*)d_in[7];
    const float* Wc1      = (const float*)d_in[8];
    const float* bc1      = (const float*)d_in[9];
    const float* Wc2      = (const float*)d_in[10];
    const float* bc2      = (const float*)d_in[11];
    const float* h_other  = (const float*)d_in[12];
    float* out = (float*)d_out;

    int n = in_sizes[0] / HD;      // nodes
    int e = in_sizes[2];           // edges
    const int* rowp = eidx;
    const int* colp = eidx + e;
    int nb = (n + 1023) / 1024;    // scan blocks (<=128)

    // CSR build (4 kernels)
    k_prep<<<400, 256>>>(n);
    k_deg_hist<<<(e + 255) / 256, 256>>>(rowp, eattr, e);
    k_scan1<<<nb, 256>>>(n);               // scan + dinv + fused final scan
    k_fill<<<(e + 255) / 256, 256>>>(rowp, colp, eattr, e);
    // layer 1 gemm
    k_gemm<<<(n + 127) / 128, 256>>>(x, W1, n);
    // fused: layer-1 agg + layer-2 gemm
    k_agg_gemm<<<(n + 127) / 128, 256>>>(b1, W2, n, e);
    // layer-2 agg + pool
    k_agg_pool<<<(n + 7) / 8, 256>>>(b2, n, e);
    // head
    k_head<<<1, 64>>>(Wc1, bc1, Wc2, bc2, h_other, out, n);
}

// round 13
// speedup vs baseline: 1.1176x; 1.1176x over previous
#include <cuda_runtime.h>
#include <cuda_fp16.h>
#include <mma.h>

using namespace nvcuda;

#define NMAX 100000
#define EMAX 1600000
#define HD 64

// Scratch (device globals — allocation-free per harness rules)
__device__ float  g_deg[NMAX];            // degree, then dinv (in place)
__device__ __half g_hwh [NMAX * HD];      // layer-1 h @ W1 (fp16)
__device__ __half g_hwh2[NMAX * HD];      // layer-2 h1 @ W2 (fp16)
__device__ __half g_h1 [NMAX * HD];       // post-relu layer-1 output (fp16)
__device__ float  g_pool[HD];             // feature sums for mean pool
// CSR build
__device__ int    g_cnt [NMAX];           // per-row edge count
__device__ int    g_slot[EMAX];           // per-edge within-row slot (from deg_hist)
__device__ int    g_start[NMAX + 1];      // row offsets (chunk-local; add g_boff)
__device__ int    g_bsum[128];            // scan partials
__device__ int    g_boff[128];            // scan partial offsets
__device__ int    g_done;                 // scan last-block detector
__device__ int2   g_edat[EMAX];           // (col, norm-bits) in row-grouped order

// ---------------------------------------------------------------------------
__global__ void k_prep(int n) {
    int i = blockIdx.x * blockDim.x + threadIdx.x;
    int stride = gridDim.x * blockDim.x;
    for (int j = i; j < n; j += stride) { g_cnt[j] = 0; g_deg[j] = 1.0f; }
    if (i < HD) g_pool[i] = 0.f;
    if (i == 0) g_done = 0;
}

// deg[row] += attr ; slot[i] = cnt[row]++  (slot reused by k_fill: no 2nd atomic)
__global__ void k_deg_hist(const int* __restrict__ rowp, const float* __restrict__ attr, int e) {
    int i = blockIdx.x * blockDim.x + threadIdx.x;
    if (i < e) {
        int r = rowp[i];
        atomicAdd(&g_deg[r], attr[i]);
        g_slot[i] = atomicAdd(&g_cnt[r], 1);
    }
}

// ---------------------------------------------------------------------------
// Single-kernel scan: per-1024-chunk exclusive scan of g_cnt into g_start,
// fused dinv; LAST finishing block scans the <=128 chunk totals into g_boff.
__global__ void k_scan1(int n) {
    __shared__ int ts[256];
    __shared__ int s_isLast;
    int tid = threadIdx.x;
    int base = blockIdx.x * 1024 + tid * 4;
    int v[4]; int s = 0;
#pragma unroll
    for (int i = 0; i < 4; i++) {
        int idx = base + i;
        v[i] = (idx < n) ? g_cnt[idx] : 0;
        s += v[i];
        if (idx < n) g_deg[idx] = rsqrtf(g_deg[idx]);   // fused dinv
    }
    ts[tid] = s;
    __syncthreads();
    for (int off = 1; off < 256; off <<= 1) {
        int y = (tid >= off) ? ts[tid - off] : 0;
        __syncthreads();
        ts[tid] += y;
        __syncthreads();
    }
    int run = ts[tid] - s;   // exclusive within chunk
#pragma unroll
    for (int i = 0; i < 4; i++) {
        int idx = base + i;
        if (idx < n) g_start[idx] = run;
        run += v[i];
    }
    if (tid == 255) g_bsum[blockIdx.x] = ts[255];
    __syncthreads();
    if (tid == 0) {
        __threadfence();
        s_isLast = (atomicAdd(&g_done, 1) == (int)gridDim.x - 1);
    }
    __syncthreads();
    if (s_isLast && tid < 32) {
        int nb = gridDim.x;
        volatile const int* bs = g_bsum;
        int w[4]; int sum = 0;
#pragma unroll
        for (int i = 0; i < 4; i++) {
            int idx = tid * 4 + i;
            w[i] = (idx < nb) ? bs[idx] : 0;
            sum += w[i];
        }
        int inc = sum;
#pragma unroll
        for (int off = 1; off < 32; off <<= 1) {
            int y = __shfl_up_sync(0xFFFFFFFFu, inc, off);
            if (tid >= off) inc += y;
        }
        int r2 = inc - sum;
#pragma unroll
        for (int i = 0; i < 4; i++) {
            int idx = tid * 4 + i;
            if (idx < nb) g_boff[idx] = r2;
            r2 += w[i];
        }
    }
}

// fill CSR: pos = start[r]+boff+slot[i]  (atomic-free)
__global__ void k_fill(const int* __restrict__ rowp, const int* __restrict__ colp,
                       const float* __restrict__ attr, int e) {
    int i = blockIdx.x * blockDim.x + threadIdx.x;
    if (i < e) {
        int r = rowp[i], c = colp[i];
        int pos = g_start[r] + g_boff[r >> 10] + g_slot[i];
        float nrm = g_deg[r] * attr[i] * g_deg[c];
        g_edat[pos] = make_int2(c, __float_as_int(nrm));
    }
}

// row range helper (boff applied on the fly; node==n-1 end comes from e)
__device__ __forceinline__ int row_start(int node) {
    return g_start[node] + g_boff[node >> 10];
}

// ---------------------------------------------------------------------------
// GEMM (tensor core): out = in @ W (fp16 in, fp32 acc, fp16 out).
// 256 threads = 8 warps; 128 rows/block; warp = 16 rows x 64 cols.
// XLD = 80 halves (160 B): every wmma fragment pointer is 32-byte aligned.
#define XLD 80
__global__ void __launch_bounds__(256) k_gemm(const float* __restrict__ inp,
                                              const float* __restrict__ W,
                                              int use_h1, int n) {
    __shared__ __align__(32) __half sW[64 * XLD];
    __shared__ __align__(32) __half sX[128 * XLD];
    __shared__ __align__(16) float  sOut[8][16 * 16];
    int tid = threadIdx.x;
    int wid = tid >> 5, lane = tid & 31;

    for (int j = tid; j < 1024; j += 256) {
        int r = j >> 4, c4 = (j & 15) * 4;
        float4 v = *(const float4*)(W + r * 64 + c4);
        __half2* d = (__half2*)&sW[r * XLD + c4];
        d[0] = __floats2half2_rn(v.x, v.y);
        d[1] = __floats2half2_rn(v.z, v.w);
    }
    int rowBase = blockIdx.x * 128;
    if (use_h1) {
        // fp16 rows: 128 rows x 8 chunks of 8 halves (16 B each)
        for (int j = tid; j < 1024; j += 256) {
            int r = j >> 3, c8 = (j & 7) * 8;
            int gr = rowBase + r;
            uint4 v = (gr < n) ? *(const uint4*)(g_h1 + (size_t)gr * 64 + c8)
                               : make_uint4(0u, 0u, 0u, 0u);
            *(uint4*)&sX[r * XLD + c8] = v;
        }
    } else {
        for (int j = tid; j < 2048; j += 256) {
            int r = j >> 4, c4 = (j & 15) * 4;
            int gr = rowBase + r;
            float4 v = (gr < n) ? *(const float4*)(inp + (size_t)gr * 64 + c4)
                                : make_float4(0.f, 0.f, 0.f, 0.f);
            __half2* d = (__half2*)&sX[r * XLD + c4];
            d[0] = __floats2half2_rn(v.x, v.y);
            d[1] = __floats2half2_rn(v.z, v.w);
        }
    }
    __syncthreads();

    wmma::fragment<wmma::accumulator, 16, 16, 16, float> acc[4];
#pragma unroll
    for (int t = 0; t < 4; t++) wmma::fill_fragment(acc[t], 0.f);
#pragma unroll
    for (int kk = 0; kk < 4; kk++) {
        wmma::fragment<wmma::matrix_a, 16, 16, 16, __half, wmma::row_major> a;
        wmma::load_matrix_sync(a, &sX[(wid * 16) * XLD + kk * 16], XLD);
#pragma unroll
        for (int t = 0; t < 4; t++) {
            wmma::fragment<wmma::matrix_b, 16, 16, 16, __half, wmma::row_major> b;
            wmma::load_matrix_sync(b, &sW[(kk * 16) * XLD + t * 16], XLD);
            wmma::mma_sync(acc[t], a, b, acc[t]);
        }
    }

    __half* dstbuf = use_h1 ? g_hwh2 : g_hwh;
    int r0 = rowBase + wid * 16;
    int rr = lane >> 1, cc = (lane & 1) * 8;
#pragma unroll
    for (int t = 0; t < 4; t++) {
        wmma::store_matrix_sync(sOut[wid], acc[t], 16, wmma::mem_row_major);
        __syncwarp();
        if (r0 + rr < n) {
            const float* src = &sOut[wid][rr * 16 + cc];
            __half2 h0 = __floats2half2_rn(src[0], src[1]);
            __half2 h1 = __floats2half2_rn(src[2], src[3]);
            __half2 h2 = __floats2half2_rn(src[4], src[5]);
            __half2 h3 = __floats2half2_rn(src[6], src[7]);
            uint4 u;
            u.x = *(unsigned int*)&h0; u.y = *(unsigned int*)&h1;
            u.z = *(unsigned int*)&h2; u.w = *(unsigned int*)&h3;
            *(uint4*)&dstbuf[(size_t)(r0 + rr) * 64 + t * 16 + cc] = u;
        }
        __syncwarp();
    }
}

// ---------------------------------------------------------------------------
// Aggregation: warp per node (latency hidden by 100k independent warps).
// layer1 (layer2=0): reads g_hwh, writes g_h1 fp16.
// layer2 (layer2=1): reads g_hwh2, block-reduces into g_pool.
__global__ void __launch_bounds__(256) k_agg(const float* __restrict__ bias,
                                             int layer2, int n, int e) {
    int lane = threadIdx.x & 31;
    int wid  = threadIdx.x >> 5;
    int node = blockIdx.x * 8 + wid;
    const __half2* hwh2 = (const __half2*)(layer2 ? g_hwh2 : g_hwh);

    float2 acc = make_float2(0.f, 0.f);
    if (node < n) {
        int s   = row_start(node);
        int end = (node == n - 1) ? e : row_start(node + 1);
        int j = s;
        for (; j + 4 <= end; j += 4) {
            int2 e0 = g_edat[j],     e1 = g_edat[j + 1];
            int2 e2 = g_edat[j + 2], e3 = g_edat[j + 3];
            float2 f0 = __half22float2(hwh2[(size_t)e0.x * 32 + lane]);
            float2 f1 = __half22float2(hwh2[(size_t)e1.x * 32 + lane]);
            float2 f2 = __half22float2(hwh2[(size_t)e2.x * 32 + lane]);
            float2 f3 = __half22float2(hwh2[(size_t)e3.x * 32 + lane]);
            float n0 = __int_as_float(e0.y), n1 = __int_as_float(e1.y);
            float n2 = __int_as_float(e2.y), n3 = __int_as_float(e3.y);
            acc.x += n0 * f0.x + n1 * f1.x + n2 * f2.x + n3 * f3.x;
            acc.y += n0 * f0.y + n1 * f1.y + n2 * f2.y + n3 * f3.y;
        }
        for (; j < end; j++) {
            int2 ed = g_edat[j];
            float2 f = __half22float2(hwh2[(size_t)ed.x * 32 + lane]);
            float nm = __int_as_float(ed.y);
            acc.x += nm * f.x;
            acc.y += nm * f.y;
        }
        float d  = g_deg[node];
        float sl = d * d;
        float2 hw = __half22float2(hwh2[(size_t)node * 32 + lane]);
        float2 b  = *(const float2*)&bias[lane * 2];
        acc.x = fmaxf(acc.x + sl * hw.x + b.x, 0.f);
        acc.y = fmaxf(acc.y + sl * hw.y + b.y, 0.f);
        if (!layer2)
            *(__half2*)&g_h1[(size_t)node * 64 + lane * 2] = __floats2half2_rn(acc.x, acc.y);
    }

    if (layer2) {
        __shared__ float2 sred[256];
        sred[threadIdx.x] = acc;
        __syncthreads();
        if (wid == 0) {
            float2 t = sred[lane];
#pragma unroll
            for (int w = 1; w < 8; w++) {
                float2 v = sred[w * 32 + lane];
                t.x += v.x; t.y += v.y;
            }
            float* dst = &g_pool[lane * 2];
            asm volatile("red.global.add.v2.f32 [%0], {%1,%2};"
                         :: "l"(dst), "f"(t.x), "f"(t.y) : "memory");
        }
    }
}

// ---------------------------------------------------------------------------
// head: z = [pool/n, h_other];  out = relu(z@Wc1+bc1) @ Wc2 + bc2
__global__ void k_head(const float* __restrict__ Wc1, const float* __restrict__ bc1,
                       const float* __restrict__ Wc2, const float* __restrict__ bc2,
                       const float* __restrict__ h_other, float* __restrict__ out, int n) {
    __shared__ float z[128];
    __shared__ float hid[64];
    int t = threadIdx.x;
    if (t < 64) {
        z[t]      = g_pool[t] / (float)n;
        z[64 + t] = h_other[t];
    }
    __syncthreads();
    if (t < 64) {
        float s = bc1[t];
#pragma unroll 8
        for (int i = 0; i < 128; i++) s += z[i] * Wc1[i * 64 + t];
        hid[t] = fmaxf(s, 0.f);
    }
    __syncthreads();
    if (t < 3) {
        float s = bc2[t];
#pragma unroll
        for (int j = 0; j < 64; j++) s += hid[j] * Wc2[j * 3 + t];
        out[t] = s;
    }
}

// ---------------------------------------------------------------------------
extern "C" void kernel_launch(void* const* d_in, const int* in_sizes, int n_in,
                              void* d_out, int out_size) {
    const float* x        = (const float*)d_in[0];
    const int*   eidx     = (const int*)  d_in[1];
    const float* eattr    = (const float*)d_in[2];
    // d_in[3] = batch (unused; single graph)
    const float* W1       = (const float*)d_in[4];
    const float* b1       = (const float*)d_in[5];
    const float* W2       = (const float*)d_in[6];
    const float* b2       = (const float*)d_in[7];
    const float* Wc1      = (const float*)d_in[8];
    const float* bc1      = (const float*)d_in[9];
    const float* Wc2      = (const float*)d_in[10];
    const float* bc2      = (const float*)d_in[11];
    const float* h_other  = (const float*)d_in[12];
    float* out = (float*)d_out;

    int n = in_sizes[0] / HD;      // nodes
    int e = in_sizes[2];           // edges
    const int* rowp = eidx;
    const int* colp = eidx + e;
    int nb = (n + 1023) / 1024;    // scan blocks (<=128)

    // CSR build (4 kernels; fill is atomic-free via g_slot)
    k_prep<<<400, 256>>>(n);
    k_deg_hist<<<(e + 255) / 256, 256>>>(rowp, eattr, e);
    k_scan1<<<nb, 256>>>(n);               // scan + dinv + fused final scan
    k_fill<<<(e + 255) / 256, 256>>>(rowp, colp, eattr, e);
    // layer 1
    k_gemm<<<(n + 127) / 128, 256>>>(x, W1, 0, n);
    k_agg<<<(n + 7) / 8, 256>>>(b1, 0, n, e);
    // layer 2 (+ pool)
    k_gemm<<<(n + 127) / 128, 256>>>(x, W2, 1, n);
    k_agg<<<(n + 7) / 8, 256>>>(b2, 1, n, e);
    // head
    k_head<<<1, 64>>>(Wc1, bc1, Wc2, bc2, h_other, out, n);
}

// round 14
// speedup vs baseline: 1.1936x; 1.0680x over previous
#include <cuda_runtime.h>
#include <cuda_fp16.h>
#include <mma.h>

using namespace nvcuda;

#define NMAX 100000
#define EMAX 1600000
#define HD 64

// Scratch (device globals — allocation-free per harness rules).
// State contract: all counters/accumulators are zero / deg==1.0 at entry
// (zero-init at module load == deg restored by agg-2, cnt by scan1, pool by
// head, done by scan1's last block) — every launch does identical work and
// leaves the same clean state behind.
__device__ float  g_deg[NMAX];            // 0 at load... see k_deg_hist note
__device__ __half g_hwh[NMAX * HD];       // h @ W (both layers, reused)
__device__ __half g_h1 [NMAX * HD];       // post-relu layer-1 output (fp16)
__device__ float  g_pool[HD];             // feature sums for mean pool
// CSR build
__device__ int    g_cnt [NMAX];           // per-row edge count
__device__ int    g_slot[EMAX];           // per-edge within-row slot
__device__ int    g_start[NMAX + 1];      // row offsets (chunk-local; add g_boff)
__device__ int    g_bsum[128];            // scan partials
__device__ int    g_boff[128];            // scan partial offsets
__device__ int    g_done;                 // scan last-block detector
__device__ int2   g_edat[EMAX];           // (col, norm-bits) in row-grouped order

// ---------------------------------------------------------------------------
// deg[row] += attr ; slot[i] = cnt[row]++
// g_deg entries are 1.0 at entry EXCEPT the very first launch (zero-init).
// To make deg = 1 + sum(attr) hold from a 0-initialized state too, the +1 is
// folded into k_scan1's rsqrt instead: deg_hist accumulates sum(attr) on top
// of 0, scan1 computes rsqrt(deg + 1). agg-2 restores deg to 0.
__global__ void k_deg_hist(const int* __restrict__ rowp, const float* __restrict__ attr, int e) {
    int i = blockIdx.x * blockDim.x + threadIdx.x;
    if (i < e) {
        int r = rowp[i];
        atomicAdd(&g_deg[r], attr[i]);
        g_slot[i] = atomicAdd(&g_cnt[r], 1);
    }
}

// ---------------------------------------------------------------------------
// Single-kernel scan: per-1024-chunk exclusive scan of g_cnt into g_start
// (zeroing g_cnt behind itself), fused dinv = rsqrt(deg+1); LAST finishing
// block scans the <=128 chunk totals into g_boff and resets g_done.
__global__ void k_scan1(int n) {
    __shared__ int ts[256];
    __shared__ int s_isLast;
    int tid = threadIdx.x;
    int base = blockIdx.x * 1024 + tid * 4;
    int v[4]; int s = 0;
#pragma unroll
    for (int i = 0; i < 4; i++) {
        int idx = base + i;
        v[i] = (idx < n) ? g_cnt[idx] : 0;
        s += v[i];
        if (idx < n) {
            g_cnt[idx] = 0;                       // restore for next launch
            g_deg[idx] = rsqrtf(g_deg[idx] + 1.0f);  // self-loop weight folded in
        }
    }
    ts[tid] = s;
    __syncthreads();
    for (int off = 1; off < 256; off <<= 1) {
        int y = (tid >= off) ? ts[tid - off] : 0;
        __syncthreads();
        ts[tid] += y;
        __syncthreads();
    }
    int run = ts[tid] - s;   // exclusive within chunk
#pragma unroll
    for (int i = 0; i < 4; i++) {
        int idx = base + i;
        if (idx < n) g_start[idx] = run;
        run += v[i];
    }
    if (tid == 255) g_bsum[blockIdx.x] = ts[255];
    __syncthreads();
    if (tid == 0) {
        __threadfence();
        s_isLast = (atomicAdd(&g_done, 1) == (int)gridDim.x - 1);
    }
    __syncthreads();
    if (s_isLast) {
        if (tid == 0) g_done = 0;                 // restore for next launch
        if (tid < 32) {
            int nb = gridDim.x;
            volatile const int* bs = g_bsum;
            int w[4]; int sum = 0;
#pragma unroll
            for (int i = 0; i < 4; i++) {
                int idx = tid * 4 + i;
                w[i] = (idx < nb) ? bs[idx] : 0;
                sum += w[i];
            }
            int inc = sum;
#pragma unroll
            for (int off = 1; off < 32; off <<= 1) {
                int y = __shfl_up_sync(0xFFFFFFFFu, inc, off);
                if (tid >= off) inc += y;
            }
            int r2 = inc - sum;
#pragma unroll
            for (int i = 0; i < 4; i++) {
                int idx = tid * 4 + i;
                if (idx < nb) g_boff[idx] = r2;
                r2 += w[i];
            }
        }
    }
}

// fill CSR: pos = start[r]+boff+slot[i]  (atomic-free)
__global__ void k_fill(const int* __restrict__ rowp, const int* __restrict__ colp,
                       const float* __restrict__ attr, int e) {
    int i = blockIdx.x * blockDim.x + threadIdx.x;
    if (i < e) {
        int r = rowp[i], c = colp[i];
        int pos = g_start[r] + g_boff[r >> 10] + g_slot[i];
        float nrm = g_deg[r] * attr[i] * g_deg[c];
        g_edat[pos] = make_int2(c, __float_as_int(nrm));
    }
}

// row range helper (boff applied on the fly; node==n-1 end comes from e)
__device__ __forceinline__ int row_start(int node) {
    return g_start[node] + g_boff[node >> 10];
}

// ---------------------------------------------------------------------------
// GEMM (tensor core): g_hwh = in @ W (fp16 in, fp32 acc, fp16 out).
// 256 threads = 8 warps; 128 rows/block; warp = 16 rows x 64 cols.
// XLD = 80 halves (160 B): every wmma fragment pointer is 32-byte aligned.
#define XLD 80
__global__ void __launch_bounds__(256) k_gemm(const float* __restrict__ inp,
                                              const float* __restrict__ W,
                                              int use_h1, int n) {
    __shared__ __align__(32) __half sW[64 * XLD];
    __shared__ __align__(32) __half sX[128 * XLD];
    __shared__ __align__(16) float  sOut[8][16 * 16];
    int tid = threadIdx.x;
    int wid = tid >> 5, lane = tid & 31;

    for (int j = tid; j < 1024; j += 256) {
        int r = j >> 4, c4 = (j & 15) * 4;
        float4 v = *(const float4*)(W + r * 64 + c4);
        __half2* d = (__half2*)&sW[r * XLD + c4];
        d[0] = __floats2half2_rn(v.x, v.y);
        d[1] = __floats2half2_rn(v.z, v.w);
    }
    int rowBase = blockIdx.x * 128;
    if (use_h1) {
        // fp16 rows: 128 rows x 8 chunks of 8 halves (16 B each)
        for (int j = tid; j < 1024; j += 256) {
            int r = j >> 3, c8 = (j & 7) * 8;
            int gr = rowBase + r;
            uint4 v = (gr < n) ? *(const uint4*)(g_h1 + (size_t)gr * 64 + c8)
                               : make_uint4(0u, 0u, 0u, 0u);
            *(uint4*)&sX[r * XLD + c8] = v;
        }
    } else {
        for (int j = tid; j < 2048; j += 256) {
            int r = j >> 4, c4 = (j & 15) * 4;
            int gr = rowBase + r;
            float4 v = (gr < n) ? *(const float4*)(inp + (size_t)gr * 64 + c4)
                                : make_float4(0.f, 0.f, 0.f, 0.f);
            __half2* d = (__half2*)&sX[r * XLD + c4];
            d[0] = __floats2half2_rn(v.x, v.y);
            d[1] = __floats2half2_rn(v.z, v.w);
        }
    }
    __syncthreads();

    wmma::fragment<wmma::accumulator, 16, 16, 16, float> acc[4];
#pragma unroll
    for (int t = 0; t < 4; t++) wmma::fill_fragment(acc[t], 0.f);
#pragma unroll
    for (int kk = 0; kk < 4; kk++) {
        wmma::fragment<wmma::matrix_a, 16, 16, 16, __half, wmma::row_major> a;
        wmma::load_matrix_sync(a, &sX[(wid * 16) * XLD + kk * 16], XLD);
#pragma unroll
        for (int t = 0; t < 4; t++) {
            wmma::fragment<wmma::matrix_b, 16, 16, 16, __half, wmma::row_major> b;
            wmma::load_matrix_sync(b, &sW[(kk * 16) * XLD + t * 16], XLD);
            wmma::mma_sync(acc[t], a, b, acc[t]);
        }
    }

    int r0 = rowBase + wid * 16;
    int rr = lane >> 1, cc = (lane & 1) * 8;
#pragma unroll
    for (int t = 0; t < 4; t++) {
        wmma::store_matrix_sync(sOut[wid], acc[t], 16, wmma::mem_row_major);
        __syncwarp();
        if (r0 + rr < n) {
            const float* src = &sOut[wid][rr * 16 + cc];
            __half2 h0 = __floats2half2_rn(src[0], src[1]);
            __half2 h1 = __floats2half2_rn(src[2], src[3]);
            __half2 h2 = __floats2half2_rn(src[4], src[5]);
            __half2 h3 = __floats2half2_rn(src[6], src[7]);
            uint4 u;
            u.x = *(unsigned int*)&h0; u.y = *(unsigned int*)&h1;
            u.z = *(unsigned int*)&h2; u.w = *(unsigned int*)&h3;
            *(uint4*)&g_hwh[(size_t)(r0 + rr) * 64 + t * 16 + cc] = u;
        }
        __syncwarp();
    }
}

// ---------------------------------------------------------------------------
// Aggregation: warp per node (latency hidden by 100k independent warps).
// layer1 (layer2=0): writes g_h1 fp16.
// layer2 (layer2=1): block-reduces into g_pool; restores g_deg[node]=0.
__global__ void __launch_bounds__(256) k_agg(const float* __restrict__ bias,
                                             int layer2, int n, int e) {
    int lane = threadIdx.x & 31;
    int wid  = threadIdx.x >> 5;
    int node = blockIdx.x * 8 + wid;
    const __half2* hwh2 = (const __half2*)g_hwh;

    float2 acc = make_float2(0.f, 0.f);
    if (node < n) {
        int s   = row_start(node);
        int end = (node == n - 1) ? e : row_start(node + 1);
        int j = s;
        for (; j + 4 <= end; j += 4) {
            int2 e0 = g_edat[j],     e1 = g_edat[j + 1];
            int2 e2 = g_edat[j + 2], e3 = g_edat[j + 3];
            float2 f0 = __half22float2(hwh2[(size_t)e0.x * 32 + lane]);
            float2 f1 = __half22float2(hwh2[(size_t)e1.x * 32 + lane]);
            float2 f2 = __half22float2(hwh2[(size_t)e2.x * 32 + lane]);
            float2 f3 = __half22float2(hwh2[(size_t)e3.x * 32 + lane]);
            float n0 = __int_as_float(e0.y), n1 = __int_as_float(e1.y);
            float n2 = __int_as_float(e2.y), n3 = __int_as_float(e3.y);
            acc.x += n0 * f0.x + n1 * f1.x + n2 * f2.x + n3 * f3.x;
            acc.y += n0 * f0.y + n1 * f1.y + n2 * f2.y + n3 * f3.y;
        }
        for (; j < end; j++) {
            int2 ed = g_edat[j];
            float2 f = __half22float2(hwh2[(size_t)ed.x * 32 + lane]);
            float nm = __int_as_float(ed.y);
            acc.x += nm * f.x;
            acc.y += nm * f.y;
        }
        float d  = g_deg[node];
        float sl = d * d;
        float2 hw = __half22float2(hwh2[(size_t)node * 32 + lane]);
        float2 b  = *(const float2*)&bias[lane * 2];
        acc.x = fmaxf(acc.x + sl * hw.x + b.x, 0.f);
        acc.y = fmaxf(acc.y + sl * hw.y + b.y, 0.f);
        if (!layer2) {
            *(__half2*)&g_h1[(size_t)node * 64 + lane * 2] = __floats2half2_rn(acc.x, acc.y);
        } else if (lane == 0) {
            g_deg[node] = 0.f;                    // restore for next launch
        }
    }

    if (layer2) {
        __shared__ float2 sred[256];
        sred[threadIdx.x] = acc;
        __syncthreads();
        if (wid == 0) {
            float2 t = sred[lane];
#pragma unroll
            for (int w = 1; w < 8; w++) {
                float2 v = sred[w * 32 + lane];
                t.x += v.x; t.y += v.y;
            }
            float* dst = &g_pool[lane * 2];
            asm volatile("red.global.add.v2.f32 [%0], {%1,%2};"
                         :: "l"(dst), "f"(t.x), "f"(t.y) : "memory");
        }
    }
}

// ---------------------------------------------------------------------------
// head: z = [pool/n, h_other];  out = relu(z@Wc1+bc1) @ Wc2 + bc2
// Also restores g_pool = 0 for the next launch.
__global__ void k_head(const float* __restrict__ Wc1, const float* __restrict__ bc1,
                       const float* __restrict__ Wc2, const float* __restrict__ bc2,
                       const float* __restrict__ h_other, float* __restrict__ out, int n) {
    __shared__ float z[128];
    __shared__ float hid[64];
    int t = threadIdx.x;
    if (t < 64) {
        z[t]      = g_pool[t] / (float)n;
        z[64 + t] = h_other[t];
        g_pool[t] = 0.f;                          // restore for next launch
    }
    __syncthreads();
    if (t < 64) {
        float s = bc1[t];
#pragma unroll 8
        for (int i = 0; i < 128; i++) s += z[i] * Wc1[i * 64 + t];
        hid[t] = fmaxf(s, 0.f);
    }
    __syncthreads();
    if (t < 3) {
        float s = bc2[t];
#pragma unroll
        for (int j = 0; j < 64; j++) s += hid[j] * Wc2[j * 3 + t];
        out[t] = s;
    }
}

// ---------------------------------------------------------------------------
extern "C" void kernel_launch(void* const* d_in, const int* in_sizes, int n_in,
                              void* d_out, int out_size) {
    const float* x        = (const float*)d_in[0];
    const int*   eidx     = (const int*)  d_in[1];
    const float* eattr    = (const float*)d_in[2];
    // d_in[3] = batch (unused; single graph)
    const float* W1       = (const float*)d_in[4];
    const float* b1       = (const float*)d_in[5];
    const float* W2       = (const float*)d_in[6];
    const float* b2       = (const float*)d_in[7];
    const float* Wc1      = (const float*)d_in[8];
    const float* bc1      = (const float*)d_in[9];
    const float* Wc2      = (const float*)d_in[10];
    const float* bc2      = (const float*)d_in[11];
    const float* h_other  = (const float*)d_in[12];
    float* out = (float*)d_out;

    int n = in_sizes[0] / HD;      // nodes
    int e = in_sizes[2];           // edges
    const int* rowp = eidx;
    const int* colp = eidx + e;
    int nb = (n + 1023) / 1024;    // scan blocks (<=128)

    // CSR build (3 kernels; state is self-restoring, no prep pass)
    k_deg_hist<<<(e + 255) / 256, 256>>>(rowp, eattr, e);
    k_scan1<<<nb, 256>>>(n);               // scan + dinv(+1) + cnt-reset + final scan
    k_fill<<<(e + 255) / 256, 256>>>(rowp, colp, eattr, e);
    // layer 1
    k_gemm<<<(n + 127) / 128, 256>>>(x, W1, 0, n);
    k_agg<<<(n + 7) / 8, 256>>>(b1, 0, n, e);
    // layer 2 (+ pool; restores deg)
    k_gemm<<<(n + 127) / 128, 256>>>(x, W2, 1, n);
    k_agg<<<(n + 7) / 8, 256>>>(b2, 1, n, e);
    // head (restores pool)
    k_head<<<1, 64>>>(Wc1, bc1, Wc2, bc2, h_other, out, n);
}

// round 16
// speedup vs baseline: 1.2968x; 1.0865x over previous
#include <cuda_runtime.h>
#include <cuda_fp16.h>
#include <mma.h>

using namespace nvcuda;

#define NMAX 100000
#define EMAX 1600000
#define HD 64

// Scratch (device globals — allocation-free per harness rules).
// Self-restoring state contract (zero-init at load == state left by a full
// launch): g_packed zeroed by scan1, g_done by scan1's last block, g_pool by
// k_head. g_deg/g_start/g_boff/g_slot/g_edat/g_hwh/g_h1 are fully rewritten
// before use each launch.
__device__ unsigned long long g_packed[NMAX];  // cnt<<40 | fixedpoint(deg)
__device__ float  g_deg[NMAX];            // dinv = rsqrt(deg+1) (written by scan1)
__device__ __half g_hwh[NMAX * HD];       // dinv[r] * (h @ W)[r]  (both layers)
__device__ __half g_h1 [NMAX * HD];       // post-relu layer-1 output (fp16)
__device__ float  g_pool[HD];             // feature sums for mean pool
__device__ int    g_slot[EMAX];           // per-edge within-row slot
__device__ int    g_start[NMAX + 1];      // row offsets (chunk-local; add g_boff)
__device__ int    g_bsum[128];            // scan partials
__device__ int    g_boff[128];            // scan partial offsets
__device__ int    g_done;                 // scan last-block detector
__device__ int2   g_edat[EMAX];           // (col, attr-bits) in row-grouped order

#define FIXP 16777216.0f     // 2^24
#define FIXP_INV (1.0f / 16777216.0f)

// ---------------------------------------------------------------------------
// ONE packed 64-bit atomic per edge: count in bits [40:64), fixed-point
// attr-sum in bits [0:40). slot comes from the returned old count.
__global__ void k_deg_hist(const int* __restrict__ rowp, const float* __restrict__ attr, int e) {
    int i = blockIdx.x * blockDim.x + threadIdx.x;
    if (i < e) {
        int r = rowp[i];
        unsigned long long inc = (1ULL << 40)
            | (unsigned long long)(attr[i] * FIXP + 0.5f);
        unsigned long long old = atomicAdd(&g_packed[r], inc);
        g_slot[i] = (int)(old >> 40);
    }
}

// ---------------------------------------------------------------------------
// Single-kernel scan: per-1024-chunk exclusive scan of counts (from g_packed,
// zeroing it behind itself) into g_start; fused dinv = rsqrt(deg+1).
// LAST finishing block scans the <=128 chunk totals into g_boff, resets g_done.
__global__ void k_scan1(int n) {
    __shared__ int ts[256];
    __shared__ int s_isLast;
    int tid = threadIdx.x;
    int base = blockIdx.x * 1024 + tid * 4;
    int v[4]; int s = 0;
#pragma unroll
    for (int i = 0; i < 4; i++) {
        int idx = base + i;
        if (idx < n) {
            unsigned long long p = g_packed[idx];
            g_packed[idx] = 0;                    // restore for next launch
            v[i] = (int)(p >> 40);
            float deg = (float)(p & ((1ULL << 40) - 1)) * FIXP_INV;
            g_deg[idx] = rsqrtf(deg + 1.0f);      // self-loop weight folded in
        } else v[i] = 0;
        s += v[i];
    }
    ts[tid] = s;
    __syncthreads();
    for (int off = 1; off < 256; off <<= 1) {
        int y = (tid >= off) ? ts[tid - off] : 0;
        __syncthreads();
        ts[tid] += y;
        __syncthreads();
    }
    int run = ts[tid] - s;   // exclusive within chunk
#pragma unroll
    for (int i = 0; i < 4; i++) {
        int idx = base + i;
        if (idx < n) g_start[idx] = run;
        run += v[i];
    }
    if (tid == 255) g_bsum[blockIdx.x] = ts[255];
    __syncthreads();
    if (tid == 0) {
        __threadfence();
        s_isLast = (atomicAdd(&g_done, 1) == (int)gridDim.x - 1);
    }
    __syncthreads();
    if (s_isLast) {
        if (tid == 0) g_done = 0;                 // restore for next launch
        if (tid < 32) {
            int nb = gridDim.x;
            volatile const int* bs = g_bsum;
            int w[4]; int sum = 0;
#pragma unroll
            for (int i = 0; i < 4; i++) {
                int idx = tid * 4 + i;
                w[i] = (idx < nb) ? bs[idx] : 0;
                sum += w[i];
            }
            int inc = sum;
#pragma unroll
            for (int off = 1; off < 32; off <<= 1) {
                int y = __shfl_up_sync(0xFFFFFFFFu, inc, off);
                if (tid >= off) inc += y;
            }
            int r2 = inc - sum;
#pragma unroll
            for (int i = 0; i < 4; i++) {
                int idx = tid * 4 + i;
                if (idx < nb) g_boff[idx] = r2;
                r2 += w[i];
            }
        }
    }
}

// fill CSR: pos = start[r]+boff+slot[i]; stores RAW (col, attr) — dinv terms
// are folded into hwh rows (dinv[col]) and the agg epilogue (dinv[row]).
__global__ void k_fill(const int* __restrict__ rowp, const int* __restrict__ colp,
                       const float* __restrict__ attr, int e) {
    int i = blockIdx.x * blockDim.x + threadIdx.x;
    if (i < e) {
        int r = rowp[i];
        int pos = g_start[r] + g_boff[r >> 10] + g_slot[i];
        g_edat[pos] = make_int2(colp[i], __float_as_int(attr[i]));
    }
}

// row range helper (boff applied on the fly; node==n-1 end comes from e)
__device__ __forceinline__ int row_start(int node) {
    return g_start[node] + g_boff[node >> 10];
}

// ---------------------------------------------------------------------------
// GEMM (tensor core): g_hwh = dinv[r] * (in @ W) (fp16 in, fp32 acc, fp16 out).
// 256 threads = 8 warps; 128 rows/block; warp = 16 rows x 64 cols.
// XLD = 80 halves (160 B): every wmma fragment pointer is 32-byte aligned.
#define XLD 80
__global__ void __launch_bounds__(256) k_gemm(const float* __restrict__ inp,
                                              const float* __restrict__ W,
                                              int use_h1, int n) {
    __shared__ __align__(32) __half sW[64 * XLD];
    __shared__ __align__(32) __half sX[128 * XLD];
    __shared__ __align__(16) float  sOut[8][16 * 16];
    int tid = threadIdx.x;
    int wid = tid >> 5, lane = tid & 31;

    for (int j = tid; j < 1024; j += 256) {
        int r = j >> 4, c4 = (j & 15) * 4;
        float4 v = *(const float4*)(W + r * 64 + c4);
        __half2* d = (__half2*)&sW[r * XLD + c4];
        d[0] = __floats2half2_rn(v.x, v.y);
        d[1] = __floats2half2_rn(v.z, v.w);
    }
    int rowBase = blockIdx.x * 128;
    if (use_h1) {
        for (int j = tid; j < 1024; j += 256) {   // 128 rows x 8 x 8-half chunks
            int r = j >> 3, c8 = (j & 7) * 8;
            int gr = rowBase + r;
            uint4 v = (gr < n) ? *(const uint4*)(g_h1 + (size_t)gr * 64 + c8)
                               : make_uint4(0u, 0u, 0u, 0u);
            *(uint4*)&sX[r * XLD + c8] = v;
        }
    } else {
        for (int j = tid; j < 2048; j += 256) {
            int r = j >> 4, c4 = (j & 15) * 4;
            int gr = rowBase + r;
            float4 v = (gr < n) ? *(const float4*)(inp + (size_t)gr * 64 + c4)
                                : make_float4(0.f, 0.f, 0.f, 0.f);
            __half2* d = (__half2*)&sX[r * XLD + c4];
            d[0] = __floats2half2_rn(v.x, v.y);
            d[1] = __floats2half2_rn(v.z, v.w);
        }
    }
    __syncthreads();

    wmma::fragment<wmma::accumulator, 16, 16, 16, float> acc[4];
#pragma unroll
    for (int t = 0; t < 4; t++) wmma::fill_fragment(acc[t], 0.f);
#pragma unroll
    for (int kk = 0; kk < 4; kk++) {
        wmma::fragment<wmma::matrix_a, 16, 16, 16, __half, wmma::row_major> a;
        wmma::load_matrix_sync(a, &sX[(wid * 16) * XLD + kk * 16], XLD);
#pragma unroll
        for (int t = 0; t < 4; t++) {
            wmma::fragment<wmma::matrix_b, 16, 16, 16, __half, wmma::row_major> b;
            wmma::load_matrix_sync(b, &sW[(kk * 16) * XLD + t * 16], XLD);
            wmma::mma_sync(acc[t], a, b, acc[t]);
        }
    }

    int r0 = rowBase + wid * 16;
    int rr = lane >> 1, cc = (lane & 1) * 8;
    float dv = (r0 + rr < n) ? g_deg[r0 + rr] : 0.f;   // dinv of this row
#pragma unroll
    for (int t = 0; t < 4; t++) {
        wmma::store_matrix_sync(sOut[wid], acc[t], 16, wmma::mem_row_major);
        __syncwarp();
        if (r0 + rr < n) {
            const float* src = &sOut[wid][rr * 16 + cc];
            __half2 h0 = __floats2half2_rn(src[0] * dv, src[1] * dv);
            __half2 h1 = __floats2half2_rn(src[2] * dv, src[3] * dv);
            __half2 h2 = __floats2half2_rn(src[4] * dv, src[5] * dv);
            __half2 h3 = __floats2half2_rn(src[6] * dv, src[7] * dv);
            uint4 u;
            u.x = *(unsigned int*)&h0; u.y = *(unsigned int*)&h1;
            u.z = *(unsigned int*)&h2; u.w = *(unsigned int*)&h3;
            *(uint4*)&g_hwh[(size_t)(r0 + rr) * 64 + t * 16 + cc] = u;
        }
        __syncwarp();
    }
}

// ---------------------------------------------------------------------------
// Aggregation: warp per node.
// out = relu(dinv[node] * (Σ attr_j * hwh'[col_j] + hwh'[node]) + bias)
// layer1 (layer2=0): writes g_h1 fp16. layer2 (layer2=1): block-reduce pool.
__global__ void __launch_bounds__(256) k_agg(const float* __restrict__ bias,
                                             int layer2, int n, int e) {
    int lane = threadIdx.x & 31;
    int wid  = threadIdx.x >> 5;
    int node = blockIdx.x * 8 + wid;
    const __half2* hwh2 = (const __half2*)g_hwh;

    float2 acc = make_float2(0.f, 0.f);
    if (node < n) {
        int s   = row_start(node);
        int end = (node == n - 1) ? e : row_start(node + 1);
        int j = s;
        for (; j + 4 <= end; j += 4) {
            int2 e0 = g_edat[j],     e1 = g_edat[j + 1];
            int2 e2 = g_edat[j + 2], e3 = g_edat[j + 3];
            float2 f0 = __half22float2(hwh2[(size_t)e0.x * 32 + lane]);
            float2 f1 = __half22float2(hwh2[(size_t)e1.x * 32 + lane]);
            float2 f2 = __half22float2(hwh2[(size_t)e2.x * 32 + lane]);
            float2 f3 = __half22float2(hwh2[(size_t)e3.x * 32 + lane]);
            float n0 = __int_as_float(e0.y), n1 = __int_as_float(e1.y);
            float n2 = __int_as_float(e2.y), n3 = __int_as_float(e3.y);
            acc.x += n0 * f0.x + n1 * f1.x + n2 * f2.x + n3 * f3.x;
            acc.y += n0 * f0.y + n1 * f1.y + n2 * f2.y + n3 * f3.y;
        }
        for (; j < end; j++) {
            int2 ed = g_edat[j];
            float2 f = __half22float2(hwh2[(size_t)ed.x * 32 + lane]);
            float nm = __int_as_float(ed.y);
            acc.x += nm * f.x;
            acc.y += nm * f.y;
        }
        float d  = g_deg[node];                   // dinv
        float2 hw = __half22float2(hwh2[(size_t)node * 32 + lane]);  // hwh'[node]
        float2 b  = *(const float2*)&bias[lane * 2];
        acc.x = fmaxf(d * (acc.x + hw.x) + b.x, 0.f);
        acc.y = fmaxf(d * (acc.y + hw.y) + b.y, 0.f);
        if (!layer2)
            *(__half2*)&g_h1[(size_t)node * 64 + lane * 2] = __floats2half2_rn(acc.x, acc.y);
    }

    if (layer2) {
        __shared__ float2 sred[256];
        sred[threadIdx.x] = acc;
        __syncthreads();
        if (wid == 0) {
            float2 t = sred[lane];
#pragma unroll
            for (int w = 1; w < 8; w++) {
                float2 v = sred[w * 32 + lane];
                t.x += v.x; t.y += v.y;
            }
            float* dst = &g_pool[lane * 2];
            asm volatile("red.global.add.v2.f32 [%0], {%1,%2};"
                         :: "l"(dst), "f"(t.x), "f"(t.y) : "memory");
        }
    }
}

// ---------------------------------------------------------------------------
// head: z = [pool/n, h_other];  out = relu(z@Wc1+bc1) @ Wc2 + bc2
// Also restores g_pool = 0 for the next launch.
__global__ void k_head(const float* __restrict__ Wc1, const float* __restrict__ bc1,
                       const float* __restrict__ Wc2, const float* __restrict__ bc2,
                       const float* __restrict__ h_other, float* __restrict__ out, int n) {
    __shared__ float z[128];
    __shared__ float hid[64];
    int t = threadIdx.x;
    if (t < 64) {
        z[t]      = g_pool[t] / (float)n;
        z[64 + t] = h_other[t];
        g_pool[t] = 0.f;                          // restore for next launch
    }
    __syncthreads();
    if (t < 64) {
        float s = bc1[t];
#pragma unroll 8
        for (int i = 0; i < 128; i++) s += z[i] * Wc1[i * 64 + t];
        hid[t] = fmaxf(s, 0.f);
    }
    __syncthreads();
    if (t < 3) {
        float s = bc2[t];
#pragma unroll
        for (int j = 0; j < 64; j++) s += hid[j] * Wc2[j * 3 + t];
        out[t] = s;
    }
}

// ---------------------------------------------------------------------------
extern "C" void kernel_launch(void* const* d_in, const int* in_sizes, int n_in,
                              void* d_out, int out_size) {
    const float* x        = (const float*)d_in[0];
    const int*   eidx     = (const int*)  d_in[1];
    const float* eattr    = (const float*)d_in[2];
    // d_in[3] = batch (unused; single graph)
    const float* W1       = (const float*)d_in[4];
    const float* b1       = (const float*)d_in[5];
    const float* W2       = (const float*)d_in[6];
    const float* b2       = (const float*)d_in[7];
    const float* Wc1      = (const float*)d_in[8];
    const float* bc1      = (const float*)d_in[9];
    const float* Wc2      = (const float*)d_in[10];
    const float* bc2      = (const float*)d_in[11];
    const float* h_other  = (const float*)d_in[12];
    float* out = (float*)d_out;

    int n = in_sizes[0] / HD;      // nodes
    int e = in_sizes[2];           // edges
    const int* rowp = eidx;
    const int* colp = eidx + e;
    int nb = (n + 1023) / 1024;    // scan blocks (<=128)

    // CSR build (3 kernels; single packed atomic, atomic-free fill)
    k_deg_hist<<<(e + 255) / 256, 256>>>(rowp, eattr, e);
    k_scan1<<<nb, 256>>>(n);               // scan + dinv + packed-reset + final scan
    k_fill<<<(e + 255) / 256, 256>>>(rowp, colp, eattr, e);
    // layer 1
    k_gemm<<<(n + 127) / 128, 256>>>(x, W1, 0, n);
    k_agg<<<(n + 7) / 8, 256>>>(b1, 0, n, e);
    // layer 2 (+ pool)
    k_gemm<<<(n + 127) / 128, 256>>>(x, W2, 1, n);
    k_agg<<<(n + 7) / 8, 256>>>(b2, 1, n, e);
    // head (restores pool)
    k_head<<<1, 64>>>(Wc1, bc1, Wc2, bc2, h_other, out, n);
}

// round 17
// speedup vs baseline: 1.3168x; 1.0154x over previous
#include <cuda_runtime.h>
#include <cuda_fp16.h>
#include <mma.h>

using namespace nvcuda;

#define NMAX 100000
#define EMAX 1600000
#define HD 64

// Scratch (device globals — allocation-free per harness rules).
// Self-restoring state contract (zero-init at load == state left by a full
// launch): g_packed zeroed by scan1, g_done by scan1's last block, g_pool by
// k_head. Everything else is fully rewritten before use each launch.
__device__ unsigned long long g_packed[NMAX];  // cnt<<40 | fixedpoint(deg)
__device__ float  g_deg[NMAX];            // dinv = rsqrt(deg+1) (written by scan1)
__device__ __half g_hwh[NMAX * HD];       // dinv[r] * (h @ W)[r]  (both layers)
__device__ __half g_h1 [NMAX * HD];       // post-relu layer-1 output (fp16)
__device__ float  g_pool[HD];             // feature sums for mean pool
__device__ int    g_slot[EMAX];           // per-edge within-row slot
__device__ int    g_start[NMAX + 1];      // row offsets (chunk-local; add g_boff)
__device__ int    g_bsum[128];            // scan partials
__device__ int    g_boff[128];            // scan partial offsets
__device__ int    g_done;                 // scan last-block detector
__device__ int2   g_edat[EMAX];           // (col, attr-bits) in row-grouped order

#define FIXP 16777216.0f     // 2^24
#define FIXP_INV (1.0f / 16777216.0f)

// ---------------------------------------------------------------------------
// ONE packed 64-bit atomic per edge: count in bits [40:64), fixed-point
// attr-sum in bits [0:40). slot comes from the returned old count.
__global__ void k_deg_hist(const int* __restrict__ rowp, const float* __restrict__ attr, int e) {
    int i = blockIdx.x * blockDim.x + threadIdx.x;
    if (i < e) {
        int r = rowp[i];
        unsigned long long inc = (1ULL << 40)
            | (unsigned long long)(attr[i] * FIXP + 0.5f);
        unsigned long long old = atomicAdd(&g_packed[r], inc);
        g_slot[i] = (int)(old >> 40);
    }
}

// ---------------------------------------------------------------------------
// Single-kernel scan: per-1024-chunk exclusive scan of counts (from g_packed,
// zeroing it behind itself) into g_start; fused dinv = rsqrt(deg+1).
// LAST finishing block scans the <=128 chunk totals into g_boff, resets g_done.
__global__ void k_scan1(int n) {
    __shared__ int ts[256];
    __shared__ int s_isLast;
    int tid = threadIdx.x;
    int base = blockIdx.x * 1024 + tid * 4;
    int v[4]; int s = 0;
#pragma unroll
    for (int i = 0; i < 4; i++) {
        int idx = base + i;
        if (idx < n) {
            unsigned long long p = g_packed[idx];
            g_packed[idx] = 0;                    // restore for next launch
            v[i] = (int)(p >> 40);
            float deg = (float)(p & ((1ULL << 40) - 1)) * FIXP_INV;
            g_deg[idx] = rsqrtf(deg + 1.0f);      // self-loop weight folded in
        } else v[i] = 0;
        s += v[i];
    }
    ts[tid] = s;
    __syncthreads();
    for (int off = 1; off < 256; off <<= 1) {
        int y = (tid >= off) ? ts[tid - off] : 0;
        __syncthreads();
        ts[tid] += y;
        __syncthreads();
    }
    int run = ts[tid] - s;   // exclusive within chunk
#pragma unroll
    for (int i = 0; i < 4; i++) {
        int idx = base + i;
        if (idx < n) g_start[idx] = run;
        run += v[i];
    }
    if (tid == 255) g_bsum[blockIdx.x] = ts[255];
    __syncthreads();
    if (tid == 0) {
        __threadfence();
        s_isLast = (atomicAdd(&g_done, 1) == (int)gridDim.x - 1);
    }
    __syncthreads();
    if (s_isLast) {
        if (tid == 0) g_done = 0;                 // restore for next launch
        if (tid < 32) {
            int nb = gridDim.x;
            volatile const int* bs = g_bsum;
            int w[4]; int sum = 0;
#pragma unroll
            for (int i = 0; i < 4; i++) {
                int idx = tid * 4 + i;
                w[i] = (idx < nb) ? bs[idx] : 0;
                sum += w[i];
            }
            int inc = sum;
#pragma unroll
            for (int off = 1; off < 32; off <<= 1) {
                int y = __shfl_up_sync(0xFFFFFFFFu, inc, off);
                if (tid >= off) inc += y;
            }
            int r2 = inc - sum;
#pragma unroll
            for (int i = 0; i < 4; i++) {
                int idx = tid * 4 + i;
                if (idx < nb) g_boff[idx] = r2;
                r2 += w[i];
            }
        }
    }
}

// row range helper (boff applied on the fly; node==n-1 end comes from e)
__device__ __forceinline__ int row_start(int node) {
    return g_start[node] + g_boff[node >> 10];
}

// ---------------------------------------------------------------------------
// FUSED fill + layer-1 GEMM (independent after scan1; overlapped by grid
// concatenation: blocks [0, gemmBlocks) = gemm, rest = fill).
//
// gemm: g_hwh = dinv[r] * (x @ W1), wmma fp16, 8 warps, 128 rows/block.
// fill: pos = start[r]+boff+slot[i]; stores RAW (col, attr).
// XLD = 80 halves (160 B): every wmma fragment pointer is 32-byte aligned.
#define XLD 80
__global__ void __launch_bounds__(256) k_fill_gemm(
        const float* __restrict__ inp, const float* __restrict__ W,
        const int* __restrict__ rowp, const int* __restrict__ colp,
        const float* __restrict__ attr, int n, int e, int gemmBlocks) {
    __shared__ __align__(32) __half sW[64 * XLD];
    __shared__ __align__(32) __half sX[128 * XLD];
    __shared__ __align__(16) float  sOut[8][16 * 16];
    int tid = threadIdx.x;

    if ((int)blockIdx.x >= gemmBlocks) {
        // ---- fill body ----
        int i = (blockIdx.x - gemmBlocks) * 256 + tid;
        if (i < e) {
            int r = rowp[i];
            int pos = g_start[r] + g_boff[r >> 10] + g_slot[i];
            g_edat[pos] = make_int2(colp[i], __float_as_int(attr[i]));
        }
        return;
    }

    // ---- gemm body (layer 1: fp32 x input) ----
    int wid = tid >> 5, lane = tid & 31;
    for (int j = tid; j < 1024; j += 256) {
        int r = j >> 4, c4 = (j & 15) * 4;
        float4 v = *(const float4*)(W + r * 64 + c4);
        __half2* d = (__half2*)&sW[r * XLD + c4];
        d[0] = __floats2half2_rn(v.x, v.y);
        d[1] = __floats2half2_rn(v.z, v.w);
    }
    int rowBase = blockIdx.x * 128;
    for (int j = tid; j < 2048; j += 256) {
        int r = j >> 4, c4 = (j & 15) * 4;
        int gr = rowBase + r;
        float4 v = (gr < n) ? *(const float4*)(inp + (size_t)gr * 64 + c4)
                            : make_float4(0.f, 0.f, 0.f, 0.f);
        __half2* d = (__half2*)&sX[r * XLD + c4];
        d[0] = __floats2half2_rn(v.x, v.y);
        d[1] = __floats2half2_rn(v.z, v.w);
    }
    __syncthreads();

    wmma::fragment<wmma::accumulator, 16, 16, 16, float> acc[4];
#pragma unroll
    for (int t = 0; t < 4; t++) wmma::fill_fragment(acc[t], 0.f);
#pragma unroll
    for (int kk = 0; kk < 4; kk++) {
        wmma::fragment<wmma::matrix_a, 16, 16, 16, __half, wmma::row_major> a;
        wmma::load_matrix_sync(a, &sX[(wid * 16) * XLD + kk * 16], XLD);
#pragma unroll
        for (int t = 0; t < 4; t++) {
            wmma::fragment<wmma::matrix_b, 16, 16, 16, __half, wmma::row_major> b;
            wmma::load_matrix_sync(b, &sW[(kk * 16) * XLD + t * 16], XLD);
            wmma::mma_sync(acc[t], a, b, acc[t]);
        }
    }

    int r0 = rowBase + wid * 16;
    int rr = lane >> 1, cc = (lane & 1) * 8;
    float dv = (r0 + rr < n) ? g_deg[r0 + rr] : 0.f;   // dinv of this row
#pragma unroll
    for (int t = 0; t < 4; t++) {
        wmma::store_matrix_sync(sOut[wid], acc[t], 16, wmma::mem_row_major);
        __syncwarp();
        if (r0 + rr < n) {
            const float* src = &sOut[wid][rr * 16 + cc];
            __half2 h0 = __floats2half2_rn(src[0] * dv, src[1] * dv);
            __half2 h1 = __floats2half2_rn(src[2] * dv, src[3] * dv);
            __half2 h2 = __floats2half2_rn(src[4] * dv, src[5] * dv);
            __half2 h3 = __floats2half2_rn(src[6] * dv, src[7] * dv);
            uint4 u;
            u.x = *(unsigned int*)&h0; u.y = *(unsigned int*)&h1;
            u.z = *(unsigned int*)&h2; u.w = *(unsigned int*)&h3;
            *(uint4*)&g_hwh[(size_t)(r0 + rr) * 64 + t * 16 + cc] = u;
        }
        __syncwarp();
    }
}

// ---------------------------------------------------------------------------
// Standalone GEMM for layer 2 (fp16 g_h1 input): g_hwh = dinv[r] * (h1 @ W2).
__global__ void __launch_bounds__(256) k_gemm2(const float* __restrict__ W, int n) {
    __shared__ __align__(32) __half sW[64 * XLD];
    __shared__ __align__(32) __half sX[128 * XLD];
    __shared__ __align__(16) float  sOut[8][16 * 16];
    int tid = threadIdx.x;
    int wid = tid >> 5, lane = tid & 31;

    for (int j = tid; j < 1024; j += 256) {
        int r = j >> 4, c4 = (j & 15) * 4;
        float4 v = *(const float4*)(W + r * 64 + c4);
        __half2* d = (__half2*)&sW[r * XLD + c4];
        d[0] = __floats2half2_rn(v.x, v.y);
        d[1] = __floats2half2_rn(v.z, v.w);
    }
    int rowBase = blockIdx.x * 128;
    for (int j = tid; j < 1024; j += 256) {   // 128 rows x 8 x 8-half chunks
        int r = j >> 3, c8 = (j & 7) * 8;
        int gr = rowBase + r;
        uint4 v = (gr < n) ? *(const uint4*)(g_h1 + (size_t)gr * 64 + c8)
                           : make_uint4(0u, 0u, 0u, 0u);
        *(uint4*)&sX[r * XLD + c8] = v;
    }
    __syncthreads();

    wmma::fragment<wmma::accumulator, 16, 16, 16, float> acc[4];
#pragma unroll
    for (int t = 0; t < 4; t++) wmma::fill_fragment(acc[t], 0.f);
#pragma unroll
    for (int kk = 0; kk < 4; kk++) {
        wmma::fragment<wmma::matrix_a, 16, 16, 16, __half, wmma::row_major> a;
        wmma::load_matrix_sync(a, &sX[(wid * 16) * XLD + kk * 16], XLD);
#pragma unroll
        for (int t = 0; t < 4; t++) {
            wmma::fragment<wmma::matrix_b, 16, 16, 16, __half, wmma::row_major> b;
            wmma::load_matrix_sync(b, &sW[(kk * 16) * XLD + t * 16], XLD);
            wmma::mma_sync(acc[t], a, b, acc[t]);
        }
    }

    int r0 = rowBase + wid * 16;
    int rr = lane >> 1, cc = (lane & 1) * 8;
    float dv = (r0 + rr < n) ? g_deg[r0 + rr] : 0.f;
#pragma unroll
    for (int t = 0; t < 4; t++) {
        wmma::store_matrix_sync(sOut[wid], acc[t], 16, wmma::mem_row_major);
        __syncwarp();
        if (r0 + rr < n) {
            const float* src = &sOut[wid][rr * 16 + cc];
            __half2 h0 = __floats2half2_rn(src[0] * dv, src[1] * dv);
            __half2 h1 = __floats2half2_rn(src[2] * dv, src[3] * dv);
            __half2 h2 = __floats2half2_rn(src[4] * dv, src[5] * dv);
            __half2 h3 = __floats2half2_rn(src[6] * dv, src[7] * dv);
            uint4 u;
            u.x = *(unsigned int*)&h0; u.y = *(unsigned int*)&h1;
            u.z = *(unsigned int*)&h2; u.w = *(unsigned int*)&h3;
            *(uint4*)&g_hwh[(size_t)(r0 + rr) * 64 + t * 16 + cc] = u;
        }
        __syncwarp();
    }
}

// ---------------------------------------------------------------------------
// Aggregation: warp per node.
// out = relu(dinv[node] * (Σ attr_j * hwh'[col_j] + hwh'[node]) + bias)
// layer1 (layer2=0): writes g_h1 fp16. layer2 (layer2=1): block-reduce pool.
__global__ void __launch_bounds__(256) k_agg(const float* __restrict__ bias,
                                             int layer2, int n, int e) {
    int lane = threadIdx.x & 31;
    int wid  = threadIdx.x >> 5;
    int node = blockIdx.x * 8 + wid;
    const __half2* hwh2 = (const __half2*)g_hwh;

    float2 acc = make_float2(0.f, 0.f);
    if (node < n) {
        int s   = row_start(node);
        int end = (node == n - 1) ? e : row_start(node + 1);
        int j = s;
        for (; j + 4 <= end; j += 4) {
            int2 e0 = g_edat[j],     e1 = g_edat[j + 1];
            int2 e2 = g_edat[j + 2], e3 = g_edat[j + 3];
            float2 f0 = __half22float2(hwh2[(size_t)e0.x * 32 + lane]);
            float2 f1 = __half22float2(hwh2[(size_t)e1.x * 32 + lane]);
            float2 f2 = __half22float2(hwh2[(size_t)e2.x * 32 + lane]);
            float2 f3 = __half22float2(hwh2[(size_t)e3.x * 32 + lane]);
            float n0 = __int_as_float(e0.y), n1 = __int_as_float(e1.y);
            float n2 = __int_as_float(e2.y), n3 = __int_as_float(e3.y);
            acc.x += n0 * f0.x + n1 * f1.x + n2 * f2.x + n3 * f3.x;
            acc.y += n0 * f0.y + n1 * f1.y + n2 * f2.y + n3 * f3.y;
        }
        for (; j < end; j++) {
            int2 ed = g_edat[j];
            float2 f = __half22float2(hwh2[(size_t)ed.x * 32 + lane]);
            float nm = __int_as_float(ed.y);
            acc.x += nm * f.x;
            acc.y += nm * f.y;
        }
        float d  = g_deg[node];                   // dinv
        float2 hw = __half22float2(hwh2[(size_t)node * 32 + lane]);  // hwh'[node]
        float2 b  = *(const float2*)&bias[lane * 2];
        acc.x = fmaxf(d * (acc.x + hw.x) + b.x, 0.f);
        acc.y = fmaxf(d * (acc.y + hw.y) + b.y, 0.f);
        if (!layer2)
            *(__half2*)&g_h1[(size_t)node * 64 + lane * 2] = __floats2half2_rn(acc.x, acc.y);
    }

    if (layer2) {
        __shared__ float2 sred[256];
        sred[threadIdx.x] = acc;
        __syncthreads();
        if (wid == 0) {
            float2 t = sred[lane];
#pragma unroll
            for (int w = 1; w < 8; w++) {
                float2 v = sred[w * 32 + lane];
                t.x += v.x; t.y += v.y;
            }
            float* dst = &g_pool[lane * 2];
            asm volatile("red.global.add.v2.f32 [%0], {%1,%2};"
                         :: "l"(dst), "f"(t.x), "f"(t.y) : "memory");
        }
    }
}

// ---------------------------------------------------------------------------
// head: z = [pool/n, h_other];  out = relu(z@Wc1+bc1) @ Wc2 + bc2
// Also restores g_pool = 0 for the next launch.
__global__ void k_head(const float* __restrict__ Wc1, const float* __restrict__ bc1,
                       const float* __restrict__ Wc2, const float* __restrict__ bc2,
                       const float* __restrict__ h_other, float* __restrict__ out, int n) {
    __shared__ float z[128];
    __shared__ float hid[64];
    int t = threadIdx.x;
    if (t < 64) {
        z[t]      = g_pool[t] / (float)n;
        z[64 + t] = h_other[t];
        g_pool[t] = 0.f;                          // restore for next launch
    }
    __syncthreads();
    if (t < 64) {
        float s = bc1[t];
#pragma unroll 8
        for (int i = 0; i < 128; i++) s += z[i] * Wc1[i * 64 + t];
        hid[t] = fmaxf(s, 0.f);
    }
    __syncthreads();
    if (t < 3) {
        float s = bc2[t];
#pragma unroll
        for (int j = 0; j < 64; j++) s += hid[j] * Wc2[j * 3 + t];
        out[t] = s;
    }
}

// ---------------------------------------------------------------------------
extern "C" void kernel_launch(void* const* d_in, const int* in_sizes, int n_in,
                              void* d_out, int out_size) {
    const float* x        = (const float*)d_in[0];
    const int*   eidx     = (const int*)  d_in[1];
    const float* eattr    = (const float*)d_in[2];
    // d_in[3] = batch (unused; single graph)
    const float* W1       = (const float*)d_in[4];
    const float* b1       = (const float*)d_in[5];
    const float* W2       = (const float*)d_in[6];
    const float* b2       = (const float*)d_in[7];
    const float* Wc1      = (const float*)d_in[8];
    const float* bc1      = (const float*)d_in[9];
    const float* Wc2      = (const float*)d_in[10];
    const float* bc2      = (const float*)d_in[11];
    const float* h_other  = (const float*)d_in[12];
    float* out = (float*)d_out;

    int n = in_sizes[0] / HD;      // nodes
    int e = in_sizes[2];           // edges
    const int* rowp = eidx;
    const int* colp = eidx + e;
    int nb = (n + 1023) / 1024;    // scan blocks (<=128)
    int gemmBlocks = (n + 127) / 128;
    int fillBlocks = (e + 255) / 256;

    // CSR build + layer-1 gemm (fill and gemm overlapped in one grid)
    k_deg_hist<<<(e + 255) / 256, 256>>>(rowp, eattr, e);
    k_scan1<<<nb, 256>>>(n);               // scan + dinv + packed-reset + final scan
    k_fill_gemm<<<gemmBlocks + fillBlocks, 256>>>(x, W1, rowp, colp, eattr,
                                                  n, e, gemmBlocks);
    // layer 1 agg
    k_agg<<<(n + 7) / 8, 256>>>(b1, 0, n, e);
    // layer 2 (+ pool)
    k_gemm2<<<gemmBlocks, 256>>>(W2, n);
    k_agg<<<(n + 7) / 8, 256>>>(b2, 1, n, e);
    // head (restores pool)
    k_head<<<1, 64>>>(Wc1, bc1, Wc2, bc2, h_other, out, n);
}